// round 3
// baseline (speedup 1.0000x reference)
#include <cuda_runtime.h>
#include <cuda_bf16.h>

#define N_NODES  100000
#define N_EDGES  3200000
#define N_FEAT   128
#define HID      16
#define OUTD     2
#define N_GRAPHS 64

// ---------------- scratch (no allocs allowed) ----------------
__device__ __align__(128) int2  g_edges[N_EDGES];          // packed (src,dst)
__device__ __align__(128) float g_deg [N_NODES];
__device__ __align__(128) float g_dinv[N_NODES];
__device__ __align__(128) float g_ts  [N_NODES * HID];     // gather source (scaled by dinv)
__device__ __align__(128) float g_acc [N_NODES * HID];     // scatter accumulator
__device__ __align__(128) float g_ts2 [N_NODES * OUTD];
__device__ __align__(128) float g_acc2[N_NODES * OUTD];
__device__ float g_pool[N_GRAPHS * OUTD];
__device__ float g_cnt [N_GRAPHS];

// ---------------- vector L2 reductions (sm_90+) ----------------
__device__ __forceinline__ void red_add_v4(float* addr, float4 v) {
    asm volatile("red.global.add.v4.f32 [%0], {%1,%2,%3,%4};"
                 :: "l"(addr), "f"(v.x), "f"(v.y), "f"(v.z), "f"(v.w) : "memory");
}
__device__ __forceinline__ void red_add_v2(float* addr, float2 v) {
    asm volatile("red.global.add.v2.f32 [%0], {%1,%2};"
                 :: "l"(addr), "f"(v.x), "f"(v.y) : "memory");
}

// ---------------- kernels ----------------
__global__ void k_init() {
    int v = blockIdx.x * blockDim.x + threadIdx.x;
    if (v < N_NODES) g_deg[v] = 1.0f;           // self loop
    if (v < N_GRAPHS * OUTD) g_pool[v] = 0.0f;
    if (v < N_GRAPHS) g_cnt[v] = 0.0f;
}

__global__ void k_edge_setup(const int* __restrict__ ei) {
    int i = blockIdx.x * blockDim.x + threadIdx.x;
    if (i >= N_EDGES) return;
    int s = ei[i];
    int d = ei[N_EDGES + i];
    g_edges[i] = make_int2(s, d);
    atomicAdd(&g_deg[d], 1.0f);
}

__global__ void k_dinv() {
    int v = blockIdx.x * blockDim.x + threadIdx.x;
    if (v >= N_NODES) return;
    g_dinv[v] = rsqrtf(g_deg[v]);               // deg >= 1 always
}

// layer 0: ts = (x @ W0) * dinv ; acc = ts
__global__ void k_gemm0(const float* __restrict__ x, const float* __restrict__ W0) {
    __shared__ float Ws[N_FEAT * HID];          // 8KB
    for (int i = threadIdx.x; i < N_FEAT * HID; i += blockDim.x) Ws[i] = W0[i];
    __syncthreads();
    int v = blockIdx.x * blockDim.x + threadIdx.x;
    if (v >= N_NODES) return;

    float o[HID];
#pragma unroll
    for (int j = 0; j < HID; j++) o[j] = 0.0f;

    const float4* xr = (const float4*)(x + (size_t)v * N_FEAT);
#pragma unroll 4
    for (int k4 = 0; k4 < N_FEAT / 4; k4++) {
        float4 xv = xr[k4];
        const float* wr = &Ws[(k4 * 4) * HID];
#pragma unroll
        for (int j = 0; j < HID; j++) o[j] = fmaf(xv.x, wr[j],           o[j]);
#pragma unroll
        for (int j = 0; j < HID; j++) o[j] = fmaf(xv.y, wr[HID + j],     o[j]);
#pragma unroll
        for (int j = 0; j < HID; j++) o[j] = fmaf(xv.z, wr[2 * HID + j], o[j]);
#pragma unroll
        for (int j = 0; j < HID; j++) o[j] = fmaf(xv.w, wr[3 * HID + j], o[j]);
    }
    float di = g_dinv[v];
    float4* tsr  = (float4*)(g_ts  + v * HID);
    float4* accr = (float4*)(g_acc + v * HID);
#pragma unroll
    for (int q = 0; q < HID / 4; q++) {
        float4 t = make_float4(o[4*q]*di, o[4*q+1]*di, o[4*q+2]*di, o[4*q+3]*di);
        tsr[q] = t; accr[q] = t;
    }
}

// mid/last layers: h = prelu(acc_in*dinv + b_prev, a_prev); ts_out = (h @ W)*dinv; acc_out = ts_out
template <int OW>
__global__ void k_layer(const float* __restrict__ Wm, const float* __restrict__ bprev,
                        const float* __restrict__ aprev,
                        const float* __restrict__ accin,
                        float* __restrict__ tsout, float* __restrict__ accout) {
    __shared__ float Ws[HID * OW];
    __shared__ float bs[HID];
    __shared__ float as;
    for (int i = threadIdx.x; i < HID * OW; i += blockDim.x) Ws[i] = Wm[i];
    if (threadIdx.x < HID) bs[threadIdx.x] = bprev[threadIdx.x];
    if (threadIdx.x == 0) as = aprev[0];
    __syncthreads();

    int v = blockIdx.x * blockDim.x + threadIdx.x;
    if (v >= N_NODES) return;
    float di = g_dinv[v];
    float aw = as;

    float h[HID];
    const float4* ar = (const float4*)(accin + v * HID);
#pragma unroll
    for (int q = 0; q < HID / 4; q++) {
        float4 a4 = ar[q];
        float t;
        t = a4.x * di + bs[4*q+0]; h[4*q+0] = t > 0.f ? t : aw * t;
        t = a4.y * di + bs[4*q+1]; h[4*q+1] = t > 0.f ? t : aw * t;
        t = a4.z * di + bs[4*q+2]; h[4*q+2] = t > 0.f ? t : aw * t;
        t = a4.w * di + bs[4*q+3]; h[4*q+3] = t > 0.f ? t : aw * t;
    }

    float o[OW];
#pragma unroll
    for (int j = 0; j < OW; j++) o[j] = 0.0f;
#pragma unroll
    for (int k = 0; k < HID; k++) {
        float hv = h[k];
#pragma unroll
        for (int j = 0; j < OW; j++) o[j] = fmaf(hv, Ws[k * OW + j], o[j]);
    }

    if (OW == HID) {
        float4* tsr  = (float4*)(tsout  + v * OW);
        float4* accr = (float4*)(accout + v * OW);
#pragma unroll
        for (int q = 0; q < OW / 4; q++) {
            float4 t = make_float4(o[4*q]*di, o[4*q+1]*di, o[4*q+2]*di, o[4*q+3]*di);
            tsr[q] = t; accr[q] = t;
        }
    } else {
        float2 t = make_float2(o[0] * di, o[1] * di);
        *(float2*)(tsout  + v * OW) = t;
        *(float2*)(accout + v * OW) = t;
    }
}

// aggregation: acc[dst] += ts[src] over all edges
__global__ void k_agg16(const float* __restrict__ ts, float* __restrict__ acc) {
    int i = blockIdx.x * blockDim.x + threadIdx.x;
    if (i >= N_EDGES) return;
    int2 e = g_edges[i];
    const float4* s = (const float4*)(ts + (size_t)e.x * HID);
    float* d = acc + (size_t)e.y * HID;
    float4 a0 = s[0], a1 = s[1], a2 = s[2], a3 = s[3];
    red_add_v4(d + 0,  a0);
    red_add_v4(d + 4,  a1);
    red_add_v4(d + 8,  a2);
    red_add_v4(d + 12, a3);
}

__global__ void k_agg2(const float* __restrict__ ts, float* __restrict__ acc) {
    int i = blockIdx.x * blockDim.x + threadIdx.x;
    if (i >= N_EDGES) return;
    int2 e = g_edges[i];
    float2 a = *(const float2*)(ts + (size_t)e.x * OUTD);
    red_add_v2(acc + (size_t)e.y * OUTD, a);
}

// pool: o = acc2*dinv + b3, segment-sum by (sorted) batch, smem pre-reduce per block
__global__ void k_pool(const int* __restrict__ batch, const float* __restrict__ b3) {
    __shared__ float sp[N_GRAPHS * OUTD];
    __shared__ float sc[N_GRAPHS];
    for (int i = threadIdx.x; i < N_GRAPHS * OUTD; i += blockDim.x) sp[i] = 0.0f;
    for (int i = threadIdx.x; i < N_GRAPHS; i += blockDim.x) sc[i] = 0.0f;
    __syncthreads();

    int v = blockIdx.x * blockDim.x + threadIdx.x;
    if (v < N_NODES) {
        int g = batch[v];
        float di = g_dinv[v];
        float o0 = g_acc2[v * OUTD + 0] * di + b3[0];
        float o1 = g_acc2[v * OUTD + 1] * di + b3[1];
        atomicAdd(&sp[g * OUTD + 0], o0);
        atomicAdd(&sp[g * OUTD + 1], o1);
        atomicAdd(&sc[g], 1.0f);
    }
    __syncthreads();
    for (int i = threadIdx.x; i < N_GRAPHS * OUTD; i += blockDim.x)
        if (sp[i] != 0.0f) atomicAdd(&g_pool[i], sp[i]);
    for (int i = threadIdx.x; i < N_GRAPHS; i += blockDim.x)
        if (sc[i] != 0.0f) atomicAdd(&g_cnt[i], sc[i]);
}

__global__ void k_div(float* __restrict__ out) {
    int i = threadIdx.x;
    if (i >= N_GRAPHS * OUTD) return;
    int g = i / OUTD;
    out[i] = g_pool[i] / fmaxf(g_cnt[g], 1.0f);
}

// ---------------- launch ----------------
extern "C" void kernel_launch(void* const* d_in, const int* in_sizes, int n_in,
                              void* d_out, int out_size) {
    const float* x     = (const float*)d_in[0];
    const int*   ei    = (const int*)d_in[1];     // JAX x64 disabled -> int32
    const int*   batch = (const int*)d_in[2];     // int32
    const float* W0 = (const float*)d_in[3];
    const float* b0 = (const float*)d_in[4];
    const float* a0 = (const float*)d_in[5];
    const float* W1 = (const float*)d_in[6];
    const float* b1 = (const float*)d_in[7];
    const float* a1 = (const float*)d_in[8];
    const float* W2 = (const float*)d_in[9];
    const float* b2 = (const float*)d_in[10];
    const float* a2 = (const float*)d_in[11];
    const float* W3 = (const float*)d_in[12];
    const float* b3 = (const float*)d_in[13];
    float* out = (float*)d_out;

    const int T = 256;
    const int NB_N = (N_NODES + T - 1) / T;
    const int NB_E = (N_EDGES + T - 1) / T;

    float* ts  = nullptr; float* acc = nullptr;
    cudaGetSymbolAddress((void**)&ts,  g_ts);
    cudaGetSymbolAddress((void**)&acc, g_acc);
    float* ts2 = nullptr; float* acc2 = nullptr;
    cudaGetSymbolAddress((void**)&ts2,  g_ts2);
    cudaGetSymbolAddress((void**)&acc2, g_acc2);

    k_init<<<NB_N, T>>>();
    k_edge_setup<<<NB_E, T>>>(ei);
    k_dinv<<<NB_N, T>>>();

    // layer 0
    k_gemm0<<<NB_N, T>>>(x, W0);
    k_agg16<<<NB_E, T>>>(ts, acc);
    // layer 1
    k_layer<HID><<<NB_N, T>>>(W1, b0, a0, acc, ts, acc);
    k_agg16<<<NB_E, T>>>(ts, acc);
    // layer 2
    k_layer<HID><<<NB_N, T>>>(W2, b1, a1, acc, ts, acc);
    k_agg16<<<NB_E, T>>>(ts, acc);
    // layer 3 (16 -> 2, no activation after)
    k_layer<OUTD><<<NB_N, T>>>(W3, b2, a2, acc, ts2, acc2);
    k_agg2<<<NB_E, T>>>(ts2, acc2);

    k_pool<<<NB_N, T>>>(batch, b3);
    k_div<<<1, 128>>>(out);
}

// round 5
// speedup vs baseline: 1.5427x; 1.5427x over previous
#include <cuda_runtime.h>
#include <cuda_bf16.h>

#define N_NODES  100000
#define N_EDGES  3200000
#define N_FEAT   128
#define HID      16
#define OUTD     2
#define N_GRAPHS 64

#define SCAN_B   1024
#define SCAN_NB  ((N_NODES + SCAN_B - 1) / SCAN_B)   // 98

// ---------------- scratch (no allocs allowed) ----------------
__device__ __align__(128) int   g_deg   [N_NODES];
__device__ __align__(128) int   g_rowptr[N_NODES + 1];
__device__ __align__(128) int   g_cursor[N_NODES];
__device__ __align__(128) int   g_csr   [N_EDGES];
__device__ __align__(128) int   g_bsum  [SCAN_NB + 1];
__device__ __align__(128) float g_dinv  [N_NODES];
__device__ __align__(128) float g_tsA   [N_NODES * HID];
__device__ __align__(128) float g_tsB   [N_NODES * HID];
__device__ __align__(128) float g_ts2   [N_NODES * OUTD];
__device__ float g_pool[N_GRAPHS * OUTD];
__device__ float g_cnt [N_GRAPHS];

// ---------------- setup ----------------
__global__ void k_zero() {
    int v = blockIdx.x * blockDim.x + threadIdx.x;
    if (v < N_NODES) g_deg[v] = 0;
    if (v < N_GRAPHS * OUTD) g_pool[v] = 0.0f;
    if (v < N_GRAPHS) g_cnt[v] = 0.0f;
}

__global__ void k_deg(const int* __restrict__ ei) {
    int i = blockIdx.x * blockDim.x + threadIdx.x;
    if (i >= N_EDGES) return;
    atomicAdd(&g_deg[ei[N_EDGES + i]], 1);
}

// inclusive block scan -> g_rowptr (temp), block totals -> g_bsum
__global__ void k_scan1() {
    __shared__ int s[SCAN_B];
    int i = blockIdx.x * SCAN_B + threadIdx.x;
    int v = (i < N_NODES) ? g_deg[i] : 0;
    s[threadIdx.x] = v;
    __syncthreads();
#pragma unroll
    for (int off = 1; off < SCAN_B; off <<= 1) {
        int t = (threadIdx.x >= off) ? s[threadIdx.x - off] : 0;
        __syncthreads();
        s[threadIdx.x] += t;
        __syncthreads();
    }
    if (i < N_NODES) g_rowptr[i] = s[threadIdx.x];
    if (threadIdx.x == SCAN_B - 1) g_bsum[blockIdx.x] = s[threadIdx.x];
}

__global__ void k_scan2() {
    if (threadIdx.x == 0) {
        int run = 0;
        for (int b = 0; b < SCAN_NB; b++) { int t = g_bsum[b]; g_bsum[b] = run; run += t; }
    }
}

__global__ void k_scan3() {
    int i = blockIdx.x * blockDim.x + threadIdx.x;
    if (i < N_NODES) {
        int excl = g_rowptr[i] - g_deg[i] + g_bsum[i / SCAN_B];
        g_rowptr[i] = excl;
        g_cursor[i] = excl;
        g_dinv[i]   = rsqrtf((float)(g_deg[i] + 1));   // +1 self loop
    }
    if (i == 0) g_rowptr[N_NODES] = N_EDGES;
}

__global__ void k_fill(const int* __restrict__ ei) {
    int i = blockIdx.x * blockDim.x + threadIdx.x;
    if (i >= N_EDGES) return;
    int s = ei[i];
    int d = ei[N_EDGES + i];
    int pos = atomicAdd(&g_cursor[d], 1);
    g_csr[pos] = s;
}

// ---------------- layer 0: ts = (x @ W0) * dinv ----------------
__global__ void k_gemm0(const float* __restrict__ x, const float* __restrict__ W0,
                        float* __restrict__ tsout) {
    __shared__ float4 Ws4[N_FEAT * HID / 4];          // 8KB
    for (int i = threadIdx.x; i < N_FEAT * HID / 4; i += blockDim.x)
        Ws4[i] = ((const float4*)W0)[i];
    __syncthreads();
    int v = blockIdx.x * blockDim.x + threadIdx.x;
    if (v >= N_NODES) return;

    float o[HID];
#pragma unroll
    for (int j = 0; j < HID; j++) o[j] = 0.0f;

    const float4* xr = (const float4*)(x + (size_t)v * N_FEAT);
#pragma unroll 8
    for (int k4 = 0; k4 < N_FEAT / 4; k4++) {
        float4 xv = xr[k4];
        const float* xp = (const float*)&xv;
#pragma unroll
        for (int r = 0; r < 4; r++) {
            float xs = xp[r];
            int row = (4 * k4 + r) * 4;               // float4 index of W row
            float4 w0 = Ws4[row + 0], w1 = Ws4[row + 1];
            float4 w2 = Ws4[row + 2], w3 = Ws4[row + 3];
            o[0]  = fmaf(xs, w0.x, o[0]);  o[1]  = fmaf(xs, w0.y, o[1]);
            o[2]  = fmaf(xs, w0.z, o[2]);  o[3]  = fmaf(xs, w0.w, o[3]);
            o[4]  = fmaf(xs, w1.x, o[4]);  o[5]  = fmaf(xs, w1.y, o[5]);
            o[6]  = fmaf(xs, w1.z, o[6]);  o[7]  = fmaf(xs, w1.w, o[7]);
            o[8]  = fmaf(xs, w2.x, o[8]);  o[9]  = fmaf(xs, w2.y, o[9]);
            o[10] = fmaf(xs, w2.z, o[10]); o[11] = fmaf(xs, w2.w, o[11]);
            o[12] = fmaf(xs, w3.x, o[12]); o[13] = fmaf(xs, w3.y, o[13]);
            o[14] = fmaf(xs, w3.z, o[14]); o[15] = fmaf(xs, w3.w, o[15]);
        }
    }
    float di = g_dinv[v];
    float4* tsr = (float4*)(tsout + (size_t)v * HID);
#pragma unroll
    for (int q = 0; q < HID / 4; q++)
        tsr[q] = make_float4(o[4*q]*di, o[4*q+1]*di, o[4*q+2]*di, o[4*q+3]*di);
}

// ---- fused CSR aggregation + PReLU + GEMV (16->16 or 16->2) ----
// 16-lane group per node. acc = ts[v] + sum over in-edges of ts[src].
// Then h = prelu(acc*dinv + b); o = h @ W (via shuffles); ts_out = o*dinv.
template <bool LAST>
__global__ void k_agg_layer(const float* __restrict__ tsin,
                            const float* __restrict__ Wm,
                            const float* __restrict__ bprev,
                            const float* __restrict__ aprev,
                            float* __restrict__ tsout) {
    __shared__ float Ws[HID * HID];
    __shared__ float bs[HID];
    __shared__ float as;
    const int WSZ = LAST ? HID * OUTD : HID * HID;
    for (int i = threadIdx.x; i < WSZ; i += blockDim.x) Ws[i] = Wm[i];
    if (threadIdx.x < HID) bs[threadIdx.x] = bprev[threadIdx.x];
    if (threadIdx.x == 0) as = aprev[0];
    __syncthreads();

    int lane = threadIdx.x & 15;
    int v = blockIdx.x * (blockDim.x >> 4) + (threadIdx.x >> 4);
    unsigned mask = 0xFFFFu << (threadIdx.x & 16);   // own 16-lane half-warp

    int rs = g_rowptr[v];
    int re = g_rowptr[v + 1];
    float acc = tsin[(size_t)v * HID + lane];        // self loop

    int j = rs;
    for (; j + 16 <= re; j += 16) {
        int myidx = g_csr[j + lane];
        float tv[16];
#pragma unroll
        for (int t = 0; t < 16; t++) {
            int s = __shfl_sync(mask, myidx, t, 16);
            tv[t] = tsin[(size_t)s * HID + lane];
        }
#pragma unroll
        for (int t = 0; t < 16; t++) acc += tv[t];
    }
    int rem = re - j;
    if (rem > 0) {
        int myidx = (lane < rem) ? g_csr[j + lane] : 0;
        for (int t = 0; t < rem; t++) {
            int s = __shfl_sync(mask, myidx, t, 16);
            acc += tsin[(size_t)s * HID + lane];
        }
    }

    float di = g_dinv[v];
    float t0 = acc * di + bs[lane];
    float h  = t0 > 0.0f ? t0 : as * t0;

    if (!LAST) {
        float o = 0.0f;
#pragma unroll
        for (int k = 0; k < HID; k++)
            o = fmaf(__shfl_sync(mask, h, k, 16), Ws[k * HID + lane], o);
        tsout[(size_t)v * HID + lane] = o * di;
    } else {
        float o = 0.0f;
#pragma unroll
        for (int k = 0; k < HID; k++) {
            float hk = __shfl_sync(mask, h, k, 16);
            float wv = (lane < OUTD) ? Ws[k * OUTD + lane] : 0.0f;
            o = fmaf(hk, wv, o);
        }
        if (lane < OUTD) tsout[(size_t)v * OUTD + lane] = o * di;
    }
}

// ---- final CSR aggregation (width 2) fused with mean pool ----
__global__ void k_aggpool(const int* __restrict__ batch, const float* __restrict__ b3) {
    __shared__ float sp[N_GRAPHS * OUTD];
    __shared__ float sc[N_GRAPHS];
    for (int i = threadIdx.x; i < N_GRAPHS * OUTD; i += blockDim.x) sp[i] = 0.0f;
    for (int i = threadIdx.x; i < N_GRAPHS; i += blockDim.x) sc[i] = 0.0f;
    __syncthreads();

    int v = blockIdx.x * blockDim.x + threadIdx.x;
    if (v < N_NODES) {
        const float2* tsf = (const float2*)g_ts2;
        float2 a = tsf[v];                            // self loop
        int rs = g_rowptr[v], re = g_rowptr[v + 1];
        int j = rs;
        for (; j + 4 <= re; j += 4) {
            int s0 = g_csr[j], s1 = g_csr[j+1], s2 = g_csr[j+2], s3 = g_csr[j+3];
            float2 m0 = tsf[s0], m1 = tsf[s1], m2 = tsf[s2], m3 = tsf[s3];
            a.x += m0.x + m1.x + m2.x + m3.x;
            a.y += m0.y + m1.y + m2.y + m3.y;
        }
        for (; j < re; j++) { float2 m = tsf[g_csr[j]]; a.x += m.x; a.y += m.y; }

        float di = g_dinv[v];
        int g = batch[v];
        atomicAdd(&sp[g * OUTD + 0], a.x * di + b3[0]);
        atomicAdd(&sp[g * OUTD + 1], a.y * di + b3[1]);
        atomicAdd(&sc[g], 1.0f);
    }
    __syncthreads();
    for (int i = threadIdx.x; i < N_GRAPHS * OUTD; i += blockDim.x)
        if (sp[i] != 0.0f) atomicAdd(&g_pool[i], sp[i]);
    for (int i = threadIdx.x; i < N_GRAPHS; i += blockDim.x)
        if (sc[i] != 0.0f) atomicAdd(&g_cnt[i], sc[i]);
}

__global__ void k_div(float* __restrict__ out) {
    int i = threadIdx.x;
    if (i >= N_GRAPHS * OUTD) return;
    out[i] = g_pool[i] / fmaxf(g_cnt[i / OUTD], 1.0f);
}

// ---------------- launch ----------------
extern "C" void kernel_launch(void* const* d_in, const int* in_sizes, int n_in,
                              void* d_out, int out_size) {
    const float* x     = (const float*)d_in[0];
    const int*   ei    = (const int*)d_in[1];     // JAX x64 disabled -> int32
    const int*   batch = (const int*)d_in[2];
    const float* W0 = (const float*)d_in[3];
    const float* b0 = (const float*)d_in[4];
    const float* a0 = (const float*)d_in[5];
    const float* W1 = (const float*)d_in[6];
    const float* b1 = (const float*)d_in[7];
    const float* a1 = (const float*)d_in[8];
    const float* W2 = (const float*)d_in[9];
    const float* b2 = (const float*)d_in[10];
    const float* a2 = (const float*)d_in[11];
    const float* W3 = (const float*)d_in[12];
    const float* b3 = (const float*)d_in[13];
    float* out = (float*)d_out;

    const int T = 256;
    const int NB_N = (N_NODES + T - 1) / T;
    const int NB_E = (N_EDGES + T - 1) / T;
    const int NB_G = N_NODES / (T / 16);          // 6250, exact

    float* tsA = nullptr; float* tsB = nullptr; float* ts2 = nullptr;
    cudaGetSymbolAddress((void**)&tsA, g_tsA);
    cudaGetSymbolAddress((void**)&tsB, g_tsB);
    cudaGetSymbolAddress((void**)&ts2, g_ts2);

    // CSR build
    k_zero <<<NB_N, T>>>();
    k_deg  <<<NB_E, T>>>(ei);
    k_scan1<<<SCAN_NB, SCAN_B>>>();
    k_scan2<<<1, 32>>>();
    k_scan3<<<NB_N, T>>>();
    k_fill <<<NB_E, T>>>(ei);

    // layers (agg fused with next layer's transform)
    k_gemm0<<<NB_N, T>>>(x, W0, tsA);
    k_agg_layer<false><<<NB_G, T>>>(tsA, W1, b0, a0, tsB);
    k_agg_layer<false><<<NB_G, T>>>(tsB, W2, b1, a1, tsA);
    k_agg_layer<true ><<<NB_G, T>>>(tsA, W3, b2, a2, ts2);
    k_aggpool<<<NB_N, T>>>(batch, b3);
    k_div<<<1, 128>>>(out);
}

// round 6
// speedup vs baseline: 1.5716x; 1.0188x over previous
#include <cuda_runtime.h>
#include <cuda_bf16.h>

#define N_NODES  100000
#define N_EDGES  3200000
#define N_FEAT   128
#define HID      16
#define OUTD     2
#define N_GRAPHS 64

#define SCAN_B   1024
#define SCAN_NB  ((N_NODES + SCAN_B - 1) / SCAN_B)   // 98

// gemm0 tiling
#define G0_NODES 64
#define G0_PITCH 132   // floats per staged row (528B): 16B-aligned, phase-conflict-free

// ---------------- scratch (no allocs allowed) ----------------
__device__ __align__(128) int   g_deg   [N_NODES];
__device__ __align__(128) int   g_rowptr[N_NODES + 1];
__device__ __align__(128) int   g_cursor[N_NODES];
__device__ __align__(128) int   g_csr   [N_EDGES];
__device__ __align__(128) int   g_bsum  [SCAN_NB + 1];
__device__ __align__(128) float g_dinv  [N_NODES];
__device__ __align__(128) float g_tsA   [N_NODES * HID];
__device__ __align__(128) float g_tsB   [N_NODES * HID];
__device__ __align__(128) float g_ts2   [N_NODES * OUTD];
__device__ float g_pool[N_GRAPHS * OUTD];
__device__ float g_cnt [N_GRAPHS];

// ---------------- setup ----------------
__global__ void k_zero() {
    int v = blockIdx.x * blockDim.x + threadIdx.x;
    if (v < N_NODES) g_deg[v] = 0;
    if (v < N_GRAPHS * OUTD) g_pool[v] = 0.0f;
    if (v < N_GRAPHS) g_cnt[v] = 0.0f;
}

__global__ void k_deg(const int* __restrict__ ei) {
    int i = blockIdx.x * blockDim.x + threadIdx.x;
    if (i >= N_EDGES) return;
    atomicAdd(&g_deg[ei[N_EDGES + i]], 1);
}

// inclusive block scan -> g_rowptr (temp), block totals -> g_bsum
__global__ void k_scan1() {
    __shared__ int s[SCAN_B];
    int i = blockIdx.x * SCAN_B + threadIdx.x;
    int v = (i < N_NODES) ? g_deg[i] : 0;
    s[threadIdx.x] = v;
    __syncthreads();
#pragma unroll
    for (int off = 1; off < SCAN_B; off <<= 1) {
        int t = (threadIdx.x >= off) ? s[threadIdx.x - off] : 0;
        __syncthreads();
        s[threadIdx.x] += t;
        __syncthreads();
    }
    if (i < N_NODES) g_rowptr[i] = s[threadIdx.x];
    if (threadIdx.x == SCAN_B - 1) g_bsum[blockIdx.x] = s[threadIdx.x];
}

// parallel exclusive scan of the 98 block sums (one 128-thread block)
__global__ void k_scan2() {
    __shared__ int s[128];
    int t = threadIdx.x;
    int v = (t < SCAN_NB) ? g_bsum[t] : 0;
    s[t] = v;
    __syncthreads();
#pragma unroll
    for (int off = 1; off < 128; off <<= 1) {
        int u = (t >= off) ? s[t - off] : 0;
        __syncthreads();
        s[t] += u;
        __syncthreads();
    }
    if (t < SCAN_NB) g_bsum[t] = s[t] - v;   // exclusive
}

__global__ void k_scan3() {
    int i = blockIdx.x * blockDim.x + threadIdx.x;
    if (i < N_NODES) {
        int excl = g_rowptr[i] - g_deg[i] + g_bsum[i / SCAN_B];
        g_rowptr[i] = excl;
        g_cursor[i] = excl;
        g_dinv[i]   = rsqrtf((float)(g_deg[i] + 1));   // +1 self loop
    }
    if (i == 0) g_rowptr[N_NODES] = N_EDGES;
}

__global__ void k_fill(const int* __restrict__ ei) {
    int i = blockIdx.x * blockDim.x + threadIdx.x;
    if (i >= N_EDGES) return;
    int s = ei[i];
    int d = ei[N_EDGES + i];
    int pos = atomicAdd(&g_cursor[d], 1);
    g_csr[pos] = s;
}

// ---------------- layer 0: ts = (x @ W0) * dinv ----------------
// 64 threads/block, 64 nodes/block. Stage x tile into smem (coalesced),
// then thread-per-node compute from smem.
__global__ __launch_bounds__(G0_NODES) void k_gemm0(
        const float* __restrict__ x, const float* __restrict__ W0,
        float* __restrict__ tsout) {
    __shared__ float  xs[G0_NODES * G0_PITCH];        // 33.8KB
    __shared__ float4 Ws4[N_FEAT * HID / 4];          // 8KB
    int tid = threadIdx.x;
    for (int i = tid; i < N_FEAT * HID / 4; i += G0_NODES)
        Ws4[i] = ((const float4*)W0)[i];

    int base = blockIdx.x * G0_NODES;
    // stage: 64 nodes * 32 float4, coalesced over threads
    const float4* x4 = (const float4*)x;
#pragma unroll
    for (int it = 0; it < 32; it++) {
        int idx = it * G0_NODES + tid;                // 0..2047
        int n = idx >> 5;                             // node in tile
        int q = idx & 31;                             // float4 within row
        if (base + n < N_NODES) {
            float4 v = x4[(size_t)(base + n) * 32 + q];
            *(float4*)&xs[n * G0_PITCH + q * 4] = v;
        }
    }
    __syncthreads();

    int v = base + tid;
    if (v >= N_NODES) return;

    float o[HID];
#pragma unroll
    for (int j = 0; j < HID; j++) o[j] = 0.0f;

    const float* xrow = &xs[tid * G0_PITCH];
#pragma unroll 8
    for (int k4 = 0; k4 < N_FEAT / 4; k4++) {
        float4 xv = *(const float4*)&xrow[k4 * 4];
        const float* xp = (const float*)&xv;
#pragma unroll
        for (int r = 0; r < 4; r++) {
            float xs_ = xp[r];
            int row = (4 * k4 + r) * 4;               // float4 index of W row
            float4 w0 = Ws4[row + 0], w1 = Ws4[row + 1];
            float4 w2 = Ws4[row + 2], w3 = Ws4[row + 3];
            o[0]  = fmaf(xs_, w0.x, o[0]);  o[1]  = fmaf(xs_, w0.y, o[1]);
            o[2]  = fmaf(xs_, w0.z, o[2]);  o[3]  = fmaf(xs_, w0.w, o[3]);
            o[4]  = fmaf(xs_, w1.x, o[4]);  o[5]  = fmaf(xs_, w1.y, o[5]);
            o[6]  = fmaf(xs_, w1.z, o[6]);  o[7]  = fmaf(xs_, w1.w, o[7]);
            o[8]  = fmaf(xs_, w2.x, o[8]);  o[9]  = fmaf(xs_, w2.y, o[9]);
            o[10] = fmaf(xs_, w2.z, o[10]); o[11] = fmaf(xs_, w2.w, o[11]);
            o[12] = fmaf(xs_, w3.x, o[12]); o[13] = fmaf(xs_, w3.y, o[13]);
            o[14] = fmaf(xs_, w3.z, o[14]); o[15] = fmaf(xs_, w3.w, o[15]);
        }
    }
    float di = g_dinv[v];
    float4* tsr = (float4*)(tsout + (size_t)v * HID);
#pragma unroll
    for (int q = 0; q < HID / 4; q++)
        tsr[q] = make_float4(o[4*q]*di, o[4*q+1]*di, o[4*q+2]*di, o[4*q+3]*di);
}

// ---- fused CSR aggregation + PReLU + GEMV (16->16 or 16->2) ----
template <bool LAST>
__global__ void k_agg_layer(const float* __restrict__ tsin,
                            const float* __restrict__ Wm,
                            const float* __restrict__ bprev,
                            const float* __restrict__ aprev,
                            float* __restrict__ tsout) {
    __shared__ float Ws[HID * HID];
    __shared__ float bs[HID];
    __shared__ float as;
    const int WSZ = LAST ? HID * OUTD : HID * HID;
    for (int i = threadIdx.x; i < WSZ; i += blockDim.x) Ws[i] = Wm[i];
    if (threadIdx.x < HID) bs[threadIdx.x] = bprev[threadIdx.x];
    if (threadIdx.x == 0) as = aprev[0];
    __syncthreads();

    int lane = threadIdx.x & 15;
    int v = blockIdx.x * (blockDim.x >> 4) + (threadIdx.x >> 4);
    unsigned mask = 0xFFFFu << (threadIdx.x & 16);   // own 16-lane half-warp

    int rs = g_rowptr[v];
    int re = g_rowptr[v + 1];
    float acc = tsin[(size_t)v * HID + lane];        // self loop

    int j = rs;
    for (; j + 16 <= re; j += 16) {
        int myidx = g_csr[j + lane];
        float tv[16];
#pragma unroll
        for (int t = 0; t < 16; t++) {
            int s = __shfl_sync(mask, myidx, t, 16);
            tv[t] = tsin[(size_t)s * HID + lane];
        }
#pragma unroll
        for (int t = 0; t < 16; t++) acc += tv[t];
    }
    int rem = re - j;
    if (rem > 0) {
        int myidx = (lane < rem) ? g_csr[j + lane] : 0;
        for (int t = 0; t < rem; t++) {
            int s = __shfl_sync(mask, myidx, t, 16);
            acc += tsin[(size_t)s * HID + lane];
        }
    }

    float di = g_dinv[v];
    float t0 = acc * di + bs[lane];
    float h  = t0 > 0.0f ? t0 : as * t0;

    if (!LAST) {
        float o = 0.0f;
#pragma unroll
        for (int k = 0; k < HID; k++)
            o = fmaf(__shfl_sync(mask, h, k, 16), Ws[k * HID + lane], o);
        tsout[(size_t)v * HID + lane] = o * di;
    } else {
        float o = 0.0f;
#pragma unroll
        for (int k = 0; k < HID; k++) {
            float hk = __shfl_sync(mask, h, k, 16);
            float wv = (lane < OUTD) ? Ws[k * OUTD + lane] : 0.0f;
            o = fmaf(hk, wv, o);
        }
        if (lane < OUTD) tsout[(size_t)v * OUTD + lane] = o * di;
    }
}

// ---- final CSR aggregation (width 2) fused with mean pool ----
__global__ void k_aggpool(const int* __restrict__ batch, const float* __restrict__ b3) {
    __shared__ float sp[N_GRAPHS * OUTD];
    __shared__ float sc[N_GRAPHS];
    for (int i = threadIdx.x; i < N_GRAPHS * OUTD; i += blockDim.x) sp[i] = 0.0f;
    for (int i = threadIdx.x; i < N_GRAPHS; i += blockDim.x) sc[i] = 0.0f;
    __syncthreads();

    int v = blockIdx.x * blockDim.x + threadIdx.x;
    if (v < N_NODES) {
        const float2* tsf = (const float2*)g_ts2;
        float2 a = tsf[v];                            // self loop
        int rs = g_rowptr[v], re = g_rowptr[v + 1];
        int j = rs;
        for (; j + 4 <= re; j += 4) {
            int s0 = g_csr[j], s1 = g_csr[j+1], s2 = g_csr[j+2], s3 = g_csr[j+3];
            float2 m0 = tsf[s0], m1 = tsf[s1], m2 = tsf[s2], m3 = tsf[s3];
            a.x += m0.x + m1.x + m2.x + m3.x;
            a.y += m0.y + m1.y + m2.y + m3.y;
        }
        for (; j < re; j++) { float2 m = tsf[g_csr[j]]; a.x += m.x; a.y += m.y; }

        float di = g_dinv[v];
        int g = batch[v];
        atomicAdd(&sp[g * OUTD + 0], a.x * di + b3[0]);
        atomicAdd(&sp[g * OUTD + 1], a.y * di + b3[1]);
        atomicAdd(&sc[g], 1.0f);
    }
    __syncthreads();
    for (int i = threadIdx.x; i < N_GRAPHS * OUTD; i += blockDim.x)
        if (sp[i] != 0.0f) atomicAdd(&g_pool[i], sp[i]);
    for (int i = threadIdx.x; i < N_GRAPHS; i += blockDim.x)
        if (sc[i] != 0.0f) atomicAdd(&g_cnt[i], sc[i]);
}

__global__ void k_div(float* __restrict__ out) {
    int i = threadIdx.x;
    if (i >= N_GRAPHS * OUTD) return;
    out[i] = g_pool[i] / fmaxf(g_cnt[i / OUTD], 1.0f);
}

// ---------------- launch ----------------
extern "C" void kernel_launch(void* const* d_in, const int* in_sizes, int n_in,
                              void* d_out, int out_size) {
    const float* x     = (const float*)d_in[0];
    const int*   ei    = (const int*)d_in[1];     // JAX x64 disabled -> int32
    const int*   batch = (const int*)d_in[2];
    const float* W0 = (const float*)d_in[3];
    const float* b0 = (const float*)d_in[4];
    const float* a0 = (const float*)d_in[5];
    const float* W1 = (const float*)d_in[6];
    const float* b1 = (const float*)d_in[7];
    const float* a1 = (const float*)d_in[8];
    const float* W2 = (const float*)d_in[9];
    const float* b2 = (const float*)d_in[10];
    const float* a2 = (const float*)d_in[11];
    const float* W3 = (const float*)d_in[12];
    const float* b3 = (const float*)d_in[13];
    float* out = (float*)d_out;

    const int T = 256;
    const int NB_N = (N_NODES + T - 1) / T;
    const int NB_E = (N_EDGES + T - 1) / T;
    const int NB_G = N_NODES / (T / 16);          // 6250, exact
    const int NB_0 = (N_NODES + G0_NODES - 1) / G0_NODES;

    float* tsA = nullptr; float* tsB = nullptr; float* ts2 = nullptr;
    cudaGetSymbolAddress((void**)&tsA, g_tsA);
    cudaGetSymbolAddress((void**)&tsB, g_tsB);
    cudaGetSymbolAddress((void**)&ts2, g_ts2);

    // CSR build
    k_zero <<<NB_N, T>>>();
    k_deg  <<<NB_E, T>>>(ei);
    k_scan1<<<SCAN_NB, SCAN_B>>>();
    k_scan2<<<1, 128>>>();
    k_scan3<<<NB_N, T>>>();
    k_fill <<<NB_E, T>>>(ei);

    // layers (agg fused with next layer's transform)
    k_gemm0<<<NB_0, G0_NODES>>>(x, W0, tsA);
    k_agg_layer<false><<<NB_G, T>>>(tsA, W1, b0, a0, tsB);
    k_agg_layer<false><<<NB_G, T>>>(tsB, W2, b1, a1, tsA);
    k_agg_layer<true ><<<NB_G, T>>>(tsA, W3, b2, a2, ts2);
    k_aggpool<<<NB_N, T>>>(batch, b3);
    k_div<<<1, 128>>>(out);
}

// round 7
// speedup vs baseline: 1.6745x; 1.0655x over previous
#include <cuda_runtime.h>
#include <cuda_bf16.h>

#define N_NODES  100000
#define N_EDGES  3200000
#define N_FEAT   128
#define HID      16
#define OUTD     2
#define N_GRAPHS 64

#define SCAN_B   1024
#define SCAN_NB  ((N_NODES + SCAN_B - 1) / SCAN_B)   // 98

// CSR rows padded to multiple of 16 (pad slots -> dummy node N_NODES, zero row)
#define CSR_CAP  (N_EDGES + 16 * N_NODES)

// gemm0 tiling
#define G0_NODES 64
#define G0_PITCH 132

// ---------------- scratch (no allocs allowed; statics start zeroed, pipeline self-restores) ----------------
__device__ __align__(128) int   g_deg     [N_NODES];        // zeroed by k_aggpool each run
__device__ __align__(128) int   g_rowstart[N_NODES];
__device__ __align__(128) int   g_cursor  [N_NODES];
__device__ __align__(128) int   g_csr     [CSR_CAP];
__device__ __align__(128) float g_dinv    [N_NODES];
__device__ __align__(128) float g_tsA     [(N_NODES + 1) * HID];
__device__ __align__(128) float g_tsB     [(N_NODES + 1) * HID];
__device__ __align__(128) float g_ts2     [(N_NODES + 1) * OUTD];
__device__ int   g_base;                                     // zeroed by k_deg each run
__device__ float g_pool[N_GRAPHS * OUTD];                    // zeroed by k_div each run
__device__ float g_cnt [N_GRAPHS];                           // zeroed by k_div each run

// ---------------- setup ----------------
__global__ void k_deg(const int* __restrict__ ei) {
    int i = blockIdx.x * blockDim.x + threadIdx.x;
    if (i == 0) g_base = 0;
    if (i >= N_EDGES) return;
    atomicAdd(&g_deg[ei[N_EDGES + i]], 1);
}

// one-shot: block scan of padded degrees, block base via atomic (order-free),
// write rowstart/cursor/dinv, fill pad slots with dummy node
__global__ void k_scanall() {
    __shared__ int s[SCAN_B];
    __shared__ int base_sh;
    int tid = threadIdx.x;
    int i = blockIdx.x * SCAN_B + tid;
    int d  = (i < N_NODES) ? g_deg[i] : 0;
    int pd = (d + 15) & ~15;
    s[tid] = pd;
    __syncthreads();
#pragma unroll
    for (int off = 1; off < SCAN_B; off <<= 1) {
        int t = (tid >= off) ? s[tid - off] : 0;
        __syncthreads();
        s[tid] += t;
        __syncthreads();
    }
    if (tid == SCAN_B - 1) base_sh = atomicAdd(&g_base, s[tid]);
    __syncthreads();
    if (i < N_NODES) {
        int excl = base_sh + s[tid] - pd;
        g_rowstart[i] = excl;
        g_cursor[i]   = excl;
        g_dinv[i]     = rsqrtf((float)(d + 1));   // +1 self loop
        for (int p = excl + d; p < excl + pd; p++) g_csr[p] = N_NODES;
    }
}

__global__ void k_fill(const int* __restrict__ ei) {
    int i = blockIdx.x * blockDim.x + threadIdx.x;
    if (i >= N_EDGES) return;
    int s = ei[i];
    int d = ei[N_EDGES + i];
    int pos = atomicAdd(&g_cursor[d], 1);
    g_csr[pos] = s;
}

// ---------------- layer 0: ts = (x @ W0) * dinv ----------------
__global__ __launch_bounds__(G0_NODES) void k_gemm0(
        const float* __restrict__ x, const float* __restrict__ W0,
        float* __restrict__ tsout) {
    __shared__ float  xs[G0_NODES * G0_PITCH];
    __shared__ float4 Ws4[N_FEAT * HID / 4];
    int tid = threadIdx.x;
    for (int i = tid; i < N_FEAT * HID / 4; i += G0_NODES)
        Ws4[i] = ((const float4*)W0)[i];

    int base = blockIdx.x * G0_NODES;
    const float4* x4 = (const float4*)x;
#pragma unroll
    for (int it = 0; it < 32; it++) {
        int idx = it * G0_NODES + tid;
        int n = idx >> 5;
        int q = idx & 31;
        if (base + n < N_NODES) {
            float4 v = x4[(size_t)(base + n) * 32 + q];
            *(float4*)&xs[n * G0_PITCH + q * 4] = v;
        }
    }
    __syncthreads();

    if (blockIdx.x == 0 && tid < HID) tsout[(size_t)N_NODES * HID + tid] = 0.0f; // dummy row

    int v = base + tid;
    if (v >= N_NODES) return;

    float o[HID];
#pragma unroll
    for (int j = 0; j < HID; j++) o[j] = 0.0f;

    const float* xrow = &xs[tid * G0_PITCH];
#pragma unroll 8
    for (int k4 = 0; k4 < N_FEAT / 4; k4++) {
        float4 xv = *(const float4*)&xrow[k4 * 4];
        const float* xp = (const float*)&xv;
#pragma unroll
        for (int r = 0; r < 4; r++) {
            float xs_ = xp[r];
            int row = (4 * k4 + r) * 4;
            float4 w0 = Ws4[row + 0], w1 = Ws4[row + 1];
            float4 w2 = Ws4[row + 2], w3 = Ws4[row + 3];
            o[0]  = fmaf(xs_, w0.x, o[0]);  o[1]  = fmaf(xs_, w0.y, o[1]);
            o[2]  = fmaf(xs_, w0.z, o[2]);  o[3]  = fmaf(xs_, w0.w, o[3]);
            o[4]  = fmaf(xs_, w1.x, o[4]);  o[5]  = fmaf(xs_, w1.y, o[5]);
            o[6]  = fmaf(xs_, w1.z, o[6]);  o[7]  = fmaf(xs_, w1.w, o[7]);
            o[8]  = fmaf(xs_, w2.x, o[8]);  o[9]  = fmaf(xs_, w2.y, o[9]);
            o[10] = fmaf(xs_, w2.z, o[10]); o[11] = fmaf(xs_, w2.w, o[11]);
            o[12] = fmaf(xs_, w3.x, o[12]); o[13] = fmaf(xs_, w3.y, o[13]);
            o[14] = fmaf(xs_, w3.z, o[14]); o[15] = fmaf(xs_, w3.w, o[15]);
        }
    }
    float di = g_dinv[v];
    float4* tsr = (float4*)(tsout + (size_t)v * HID);
#pragma unroll
    for (int q = 0; q < HID / 4; q++)
        tsr[q] = make_float4(o[4*q]*di, o[4*q+1]*di, o[4*q+2]*di, o[4*q+3]*di);
}

// ---- fused CSR aggregation + PReLU + GEMV (16->16 or 16->2) ----
// rows padded to 16: no tail, indices via uniform int4 broadcast loads
template <bool LAST>
__global__ void k_agg_layer(const float* __restrict__ tsin,
                            const float* __restrict__ Wm,
                            const float* __restrict__ bprev,
                            const float* __restrict__ aprev,
                            float* __restrict__ tsout) {
    __shared__ float Ws[HID * HID];
    __shared__ float bs[HID];
    __shared__ float as;
    const int WSZ = LAST ? HID * OUTD : HID * HID;
    for (int i = threadIdx.x; i < WSZ; i += blockDim.x) Ws[i] = Wm[i];
    if (threadIdx.x < HID) bs[threadIdx.x] = bprev[threadIdx.x];
    if (threadIdx.x == 0) as = aprev[0];
    __syncthreads();

    if (blockIdx.x == 0) {                         // dummy row for next pass
        if (!LAST) { if (threadIdx.x < HID)  tsout[(size_t)N_NODES * HID  + threadIdx.x] = 0.0f; }
        else       { if (threadIdx.x < OUTD) tsout[(size_t)N_NODES * OUTD + threadIdx.x] = 0.0f; }
    }

    int lane = threadIdx.x & 15;
    int v = blockIdx.x * (blockDim.x >> 4) + (threadIdx.x >> 4);
    unsigned mask = 0xFFFFu << (threadIdx.x & 16);

    int rs = g_rowstart[v];
    int dg = g_deg[v];
    int re = rs + ((dg + 15) & ~15);
    float acc = tsin[(size_t)v * HID + lane];      // self loop

    for (int j = rs; j < re; j += 16) {
        const int4* cp = (const int4*)(g_csr + j); // 64B-aligned, uniform across lanes
        int4 i0 = cp[0], i1 = cp[1], i2 = cp[2], i3 = cp[3];
        int idx[16] = { i0.x, i0.y, i0.z, i0.w, i1.x, i1.y, i1.z, i1.w,
                        i2.x, i2.y, i2.z, i2.w, i3.x, i3.y, i3.z, i3.w };
        float tv[16];
#pragma unroll
        for (int t = 0; t < 16; t++) tv[t] = tsin[(size_t)idx[t] * HID + lane];
#pragma unroll
        for (int t = 0; t < 16; t++) acc += tv[t];
    }

    float di = g_dinv[v];
    float t0 = acc * di + bs[lane];
    float h  = t0 > 0.0f ? t0 : as * t0;

    if (!LAST) {
        float o = 0.0f;
#pragma unroll
        for (int k = 0; k < HID; k++)
            o = fmaf(__shfl_sync(mask, h, k, 16), Ws[k * HID + lane], o);
        tsout[(size_t)v * HID + lane] = o * di;
    } else {
        float o = 0.0f;
#pragma unroll
        for (int k = 0; k < HID; k++) {
            float hk = __shfl_sync(mask, h, k, 16);
            float wv = (lane < OUTD) ? Ws[k * OUTD + lane] : 0.0f;
            o = fmaf(hk, wv, o);
        }
        if (lane < OUTD) tsout[(size_t)v * OUTD + lane] = o * di;
    }
}

// ---- final CSR aggregation (width 2), 16 lanes/node, fused with mean pool ----
__global__ void k_aggpool(const int* __restrict__ batch, const float* __restrict__ b3) {
    __shared__ float sp[N_GRAPHS * OUTD];
    __shared__ float sc[N_GRAPHS];
    for (int i = threadIdx.x; i < N_GRAPHS * OUTD; i += blockDim.x) sp[i] = 0.0f;
    for (int i = threadIdx.x; i < N_GRAPHS; i += blockDim.x) sc[i] = 0.0f;
    __syncthreads();

    int lane = threadIdx.x & 15;
    int v = blockIdx.x * (blockDim.x >> 4) + (threadIdx.x >> 4);
    unsigned mask = 0xFFFFu << (threadIdx.x & 16);
    const float2* tsf = (const float2*)g_ts2;

    int rs = g_rowstart[v];
    int dg = g_deg[v];
    int re = rs + ((dg + 15) & ~15);

    float ax = 0.0f, ay = 0.0f;
    for (int j = rs; j < re; j += 16) {
        int s = g_csr[j + lane];                   // coalesced
        float2 m = tsf[s];                         // dummy row = 0
        ax += m.x; ay += m.y;
    }
#pragma unroll
    for (int off = 8; off > 0; off >>= 1) {
        ax += __shfl_down_sync(mask, ax, off, 16);
        ay += __shfl_down_sync(mask, ay, off, 16);
    }
    if (lane == 0) {
        float2 self = tsf[v];
        ax += self.x; ay += self.y;
        float di = g_dinv[v];
        int g = batch[v];
        atomicAdd(&sp[g * OUTD + 0], ax * di + b3[0]);
        atomicAdd(&sp[g * OUTD + 1], ay * di + b3[1]);
        atomicAdd(&sc[g], 1.0f);
        g_deg[v] = 0;                              // restore for next replay
    }
    __syncthreads();
    for (int i = threadIdx.x; i < N_GRAPHS * OUTD; i += blockDim.x)
        if (sp[i] != 0.0f) atomicAdd(&g_pool[i], sp[i]);
    for (int i = threadIdx.x; i < N_GRAPHS; i += blockDim.x)
        if (sc[i] != 0.0f) atomicAdd(&g_cnt[i], sc[i]);
}

__global__ void k_div(float* __restrict__ out) {
    int i = threadIdx.x;
    float c = (i < N_GRAPHS) ? g_cnt[i] : 0.0f;
    float p = (i < N_GRAPHS * OUTD) ? g_pool[i] : 0.0f;
    float cg = (i < N_GRAPHS * OUTD) ? g_cnt[i / OUTD] : 1.0f;
    __syncthreads();
    if (i < N_GRAPHS * OUTD) { out[i] = p / fmaxf(cg, 1.0f); g_pool[i] = 0.0f; }
    if (i < N_GRAPHS) g_cnt[i] = 0.0f;
    (void)c;
}

// ---------------- launch ----------------
extern "C" void kernel_launch(void* const* d_in, const int* in_sizes, int n_in,
                              void* d_out, int out_size) {
    const float* x     = (const float*)d_in[0];
    const int*   ei    = (const int*)d_in[1];
    const int*   batch = (const int*)d_in[2];
    const float* W0 = (const float*)d_in[3];
    const float* b0 = (const float*)d_in[4];
    const float* a0 = (const float*)d_in[5];
    const float* W1 = (const float*)d_in[6];
    const float* b1 = (const float*)d_in[7];
    const float* a1 = (const float*)d_in[8];
    const float* W2 = (const float*)d_in[9];
    const float* b2 = (const float*)d_in[10];
    const float* a2 = (const float*)d_in[11];
    const float* W3 = (const float*)d_in[12];
    const float* b3 = (const float*)d_in[13];
    float* out = (float*)d_out;

    const int T = 256;
    const int NB_E = (N_EDGES + T - 1) / T;
    const int NB_G = N_NODES / (T / 16);          // 6250, exact
    const int NB_0 = (N_NODES + G0_NODES - 1) / G0_NODES;

    float* tsA = nullptr; float* tsB = nullptr; float* ts2 = nullptr;
    cudaGetSymbolAddress((void**)&tsA, g_tsA);
    cudaGetSymbolAddress((void**)&tsB, g_tsB);
    cudaGetSymbolAddress((void**)&ts2, g_ts2);

    // CSR build (self-restoring state machine; statics start zeroed)
    k_deg    <<<NB_E, T>>>(ei);
    k_scanall<<<SCAN_NB, SCAN_B>>>();
    k_fill   <<<NB_E, T>>>(ei);

    // layers (agg fused with next layer's transform)
    k_gemm0<<<NB_0, G0_NODES>>>(x, W0, tsA);
    k_agg_layer<false><<<NB_G, T>>>(tsA, W1, b0, a0, tsB);
    k_agg_layer<false><<<NB_G, T>>>(tsB, W2, b1, a1, tsA);
    k_agg_layer<true ><<<NB_G, T>>>(tsA, W3, b2, a2, ts2);
    k_aggpool<<<NB_G, T>>>(batch, b3);
    k_div<<<1, 128>>>(out);
}